// round 13
// baseline (speedup 1.0000x reference)
#include <cuda_runtime.h>

// DySample fused: B=16, C=64, H=W=128, scale=2, groups=4
// Phase 1 (block = one (b,h) row): off = (x . w_off^T + b_off)*0.25 + init -> smem
//   (G=4 lane map: thread = 2 consecutive pixels x 8 och; LDG.64 + broadcast LDS)
// Phase 2: thread = pixel pair (2k,2k+1) x one group g x 16 channels.
//   init sign s = (g&1)? ri : rj => per-pixel tap window = s-diagonal 2x2 of the
//   3x3; the pair's union is covered by 7 LDG.64 per channel (rows rm: L,M /
//   rc: L,M,R / rp: M,R). Scalar nested lerps; STG.128 .cs stores.
//   Cold exact-repair loop handles positions escaping the predicted window.

#define HW 16384

__device__ __forceinline__ unsigned long long pack2(float a, float b) {
    unsigned long long r;
    asm("mov.b64 %0, {%1, %2};" : "=l"(r) : "f"(a), "f"(b));
    return r;
}
__device__ __forceinline__ void ffma2(unsigned long long& d,
                                      unsigned long long a, unsigned long long b) {
    asm("fma.rn.f32x2 %0, %1, %2, %0;" : "+l"(d) : "l"(a), "l"(b));
}
__device__ __forceinline__ float2 unpack2(unsigned long long v) {
    float2 f;
    asm("mov.b64 {%0, %1}, %2;" : "=f"(f.x), "=f"(f.y) : "l"(v));
    return f;
}
__device__ __forceinline__ float clampf(float v, float lo, float hi) {
    return fminf(fmaxf(v, lo), hi);
}
__device__ __forceinline__ void stcs4(float* p, float a, float b, float c, float d) {
    asm volatile("st.global.cs.v4.f32 [%0], {%1, %2, %3, %4};"
                 :: "l"(p), "f"(a), "f"(b), "f"(c), "f"(d) : "memory");
}

// ---------------------------------------------------------------------------
// Phase 2 worker, GG = g & 1 compile-time (warps uniform in g).
// ---------------------------------------------------------------------------
template <int GG>
__device__ __forceinline__ void sample_pair(
    const float* __restrict__ offs,
    const float* __restrict__ x,
    float* __restrict__ out,
    int b, int h, int g, int k)
{
    const int w0 = k << 1;
    const float fh = (float)h;
    const int hm = max(h - 1, 0), hp = min(h + 1, 127);
    const int rm = hm << 7, rc = h << 7, rp = hp << 7;
    const int colL = max(w0 - 2, 0);
    const int colM = w0;
    const int colR = min(w0 + 2, 126);
    const bool k0 = (k == 0), k63 = (k == 63);

    float WX[4][2], WY[4][2];
    int bad = 0;
    #pragma unroll
    for (int pos = 0; pos < 4; pos++) {     // pos = ri*2 + rj
        const int ri = pos >> 1, rj = pos & 1;
        const int s = GG ? ri : rj;          // compile-time
        const int o = (g << 2) + pos;
        const float2 ox2 = *reinterpret_cast<const float2*>(&offs[(o << 7) + w0]);
        const float2 oy2 = *reinterpret_cast<const float2*>(&offs[((o + 16) << 7) + w0]);
        #pragma unroll
        for (int p = 0; p < 2; p++) {
            const int wq = w0 + p;
            const float ix = clampf((float)wq + (p ? ox2.y : ox2.x), 0.0f, 127.0f);
            const float iy = clampf(fh + (p ? oy2.y : oy2.x), 0.0f, 127.0f);
            const float x0f = floorf(ix), y0f = floorf(iy);
            const float wx = ix - x0f, wy = iy - y0f;
            const int x0 = (int)x0f, y0 = (int)y0f;
            const int x1 = min(x0 + 1, 127), y1 = min(y0 + 1, 127);
            const int cx0 = s ? wq : max(wq - 1, 0);
            const int cx1 = s ? min(wq + 1, 127) : wq;
            const int cy0 = s ? h : hm, cy1 = s ? hp : h;
            const bool ok = (x0 == cx0) && (wx == 0.0f || x1 == cx1)
                         && (y0 == cy0) && (wy == 0.0f || y1 == cy1);
            if (!ok) bad |= 1 << (pos * 2 + p);
            WX[pos][p] = wx;
            WY[pos][p] = wy;
        }
    }

    const int cbase = b * 64 + (g << 4);
    const float* pb = x + (cbase << 14);
    float* db = out + (cbase << 16) + (h << 9) + (w0 << 1);   // X = 4k

    {   // fast path: 7 LDG.64 per channel serve both pixels' 4 positions
        const float* p = pb;
        float* dst = db;
        #pragma unroll 2
        for (int cc = 0; cc < 16; cc++) {
            const float2 L0 = __ldg(reinterpret_cast<const float2*>(p + rm + colL));
            const float2 M0 = __ldg(reinterpret_cast<const float2*>(p + rm + colM));
            const float2 L1 = __ldg(reinterpret_cast<const float2*>(p + rc + colL));
            const float2 M1 = __ldg(reinterpret_cast<const float2*>(p + rc + colM));
            const float2 R1 = __ldg(reinterpret_cast<const float2*>(p + rc + colR));
            const float2 M2 = __ldg(reinterpret_cast<const float2*>(p + rp + colM));
            const float2 R2 = __ldg(reinterpret_cast<const float2*>(p + rp + colR));
            const float a0 = k0 ? L0.x : L0.y;    // (rm, w0-1 clamped)
            const float a1 = k0 ? L1.x : L1.y;    // (rc, w0-1 clamped)
            const float b1 = k63 ? R1.y : R1.x;   // (rc, w0+2 clamped)
            const float b2 = k63 ? R2.y : R2.x;   // (rp, w0+2 clamped)

            float vv[4][2];
            #pragma unroll
            for (int pos = 0; pos < 4; pos++) {
                const int s = GG ? (pos >> 1) : (pos & 1);  // compile-time
                // pixel 0 (w = w0)
                {
                    const float t00 = s ? M1.x : a0,   t01 = s ? M1.y : M0.x;
                    const float t10 = s ? M2.x : a1,   t11 = s ? M2.y : M1.x;
                    const float h0 = fmaf(WX[pos][0], t01 - t00, t00);
                    const float h1 = fmaf(WX[pos][0], t11 - t10, t10);
                    vv[pos][0] = fmaf(WY[pos][0], h1 - h0, h0);
                }
                // pixel 1 (w = w0+1)
                {
                    const float t00 = s ? M1.y : M0.x, t01 = s ? b1 : M0.y;
                    const float t10 = s ? M2.y : M1.x, t11 = s ? b2 : M1.y;
                    const float h0 = fmaf(WX[pos][1], t01 - t00, t00);
                    const float h1 = fmaf(WX[pos][1], t11 - t10, t10);
                    vv[pos][1] = fmaf(WY[pos][1], h1 - h0, h0);
                }
            }
            // row Y=2h:   X = 4k .. 4k+3 = [pix0 rj0, pix0 rj1, pix1 rj0, pix1 rj1]
            stcs4(dst,       vv[0][0], vv[1][0], vv[0][1], vv[1][1]);
            stcs4(dst + 256, vv[2][0], vv[3][0], vv[2][1], vv[3][1]);
            p += HW;
            dst += 65536;
        }
    }

    if (bad) {  // cold exact repair (offset escaped predicted window)
        for (int pos = 0; pos < 4; pos++) {
            const int ri = pos >> 1, rj = pos & 1;
            const int o = (g << 2) + pos;
            for (int p_ = 0; p_ < 2; p_++) {
                if (!(bad & (1 << (pos * 2 + p_)))) continue;
                const int wq = w0 + p_;
                const float offx = offs[(o << 7) + wq];
                const float offy = offs[((o + 16) << 7) + wq];
                const float ix = clampf((float)wq + offx, 0.0f, 127.0f);
                const float iy = clampf(fh + offy, 0.0f, 127.0f);
                const float x0f = floorf(ix), y0f = floorf(iy);
                const float wx = ix - x0f, wy = iy - y0f;
                const int x0 = (int)x0f, y0 = (int)y0f;
                const int x1 = min(x0 + 1, 127), y1 = min(y0 + 1, 127);
                const float* p = pb;
                float* dst = db + ri * 256 + (p_ << 1) + rj;
                for (int cc = 0; cc < 16; cc++) {
                    const float u00 = __ldg(p + (y0 << 7) + x0);
                    const float u01 = __ldg(p + (y0 << 7) + x1);
                    const float u10 = __ldg(p + (y1 << 7) + x0);
                    const float u11 = __ldg(p + (y1 << 7) + x1);
                    *dst = (1.0f - wy) * ((1.0f - wx) * u00 + wx * u01)
                         + wy * ((1.0f - wx) * u10 + wx * u11);
                    p += HW;
                    dst += 65536;
                }
            }
        }
    }
}

__global__ __launch_bounds__(256, 4) void dysample_fused(
    const float* __restrict__ x,
    const float* __restrict__ w_off,
    const float* __restrict__ b_off,
    float* __restrict__ out)
{
    __shared__ __align__(16) float ws[64 * 32];     // [c][o]
    __shared__ __align__(16) float offs[32 * 128];  // [o][w]

    const int h   = blockIdx.x;
    const int b   = blockIdx.y;
    const int tid = threadIdx.x;

    for (int i = tid; i < 2048; i += 256) {
        int c = i >> 5, o = i & 31;
        ws[i] = __ldg(&w_off[o * 64 + c]);
    }
    __syncthreads();

    // ---------------- Phase 1: 64->32 matvec for this row (packed f32x2) ----
    {
        const int pg = tid & 63;         // pixel pair: pixels 2pg, 2pg+1
        const int og = tid >> 6;         // och group: 8 och [8og, 8og+8)
        const int p0 = pg << 1;
        const float* xb = x + ((b * 64) << 14) + (h << 7) + p0;

        unsigned long long acc[2][4];    // [pixel][och-pair]
        #pragma unroll
        for (int p = 0; p < 2; p++)
            #pragma unroll
            for (int j = 0; j < 4; j++) acc[p][j] = 0ull;

        #pragma unroll 4
        for (int c = 0; c < 64; c++) {
            const float2 xv = __ldg(reinterpret_cast<const float2*>(xb + (c << 14)));
            const ulonglong2* wq =
                reinterpret_cast<const ulonglong2*>(&ws[c * 32 + (og << 3)]);
            const ulonglong2 wA = wq[0], wB = wq[1];
            const unsigned long long xp0 = pack2(xv.x, xv.x);
            const unsigned long long xp1 = pack2(xv.y, xv.y);
            ffma2(acc[0][0], xp0, wA.x); ffma2(acc[0][1], xp0, wA.y);
            ffma2(acc[0][2], xp0, wB.x); ffma2(acc[0][3], xp0, wB.y);
            ffma2(acc[1][0], xp1, wA.x); ffma2(acc[1][1], xp1, wA.y);
            ffma2(acc[1][2], xp1, wB.x); ffma2(acc[1][3], xp1, wB.y);
        }

        #pragma unroll
        for (int j = 0; j < 4; j++) {
            const float2 f0 = unpack2(acc[0][j]);
            const float2 f1 = unpack2(acc[1][j]);
            #pragma unroll
            for (int e = 0; e < 2; e++) {
                const int o = (og << 3) + (j << 1) + e;
                const float bias = __ldg(&b_off[o]);
                const int dd = (o >> 2) & 1, ii = (o >> 1) & 1, jj = o & 1;
                const float initv = 0.25f * (float)((((dd ? ii : jj) << 1)) - 1);
                float2 v;
                v.x = ((e ? f0.y : f0.x) + bias) * 0.25f + initv;
                v.y = ((e ? f1.y : f1.x) + bias) * 0.25f + initv;
                *reinterpret_cast<float2*>(&offs[(o << 7) + p0]) = v;
            }
        }
    }
    __syncthreads();

    // ---------------- Phase 2: bilinear sampling (pixel pair) --------------
    const int k = tid & 63;
    const int g = tid >> 6;              // warp-uniform
    if ((g & 1) == 0)
        sample_pair<0>(offs, x, out, b, h, g, k);
    else
        sample_pair<1>(offs, x, out, b, h, g, k);
}

extern "C" void kernel_launch(void* const* d_in, const int* in_sizes, int n_in,
                              void* d_out, int out_size)
{
    const float* x     = (const float*)d_in[0];  // [16,64,128,128]
    const float* w_off = (const float*)d_in[1];  // [32,64]
    const float* b_off = (const float*)d_in[2];  // [32]
    float* out = (float*)d_out;                  // [16,64,256,256]

    dysample_fused<<<dim3(128, 16), 256>>>(x, w_off, b_off, out);
    (void)in_sizes; (void)n_in; (void)out_size;
}

// round 14
// speedup vs baseline: 1.0023x; 1.0023x over previous
#include <cuda_runtime.h>

// DySample fused: B=16, C=64, H=W=128, scale=2, groups=4
// Phase 1 (block = one (b,h) row): off = (x . w_off^T + b_off)*0.25 + init -> smem
//   (G=4 lane map: thread = 2 consecutive pixels x 8 och; LDG.64 + broadcast LDS)
// Phase 2: thread = pixel pair (2k,2k+1) x one group g x 16 channels.
//   init sign s = (g&1)? ri : rj. KEY: the two s=0 positions share one 2x2
//   window (rows rm/rc x cols wm/w) and the two s=1 positions share the other
//   (rc/rp x w/wp) -> compute window A, release taps, then window B.
//   7 LDG.64 per channel serve both pixels' 4 positions; STG.128 .cs stores.
//   Cold exact-repair loop handles positions escaping the predicted window.

#define HW 16384

__device__ __forceinline__ unsigned long long pack2(float a, float b) {
    unsigned long long r;
    asm("mov.b64 %0, {%1, %2};" : "=l"(r) : "f"(a), "f"(b));
    return r;
}
__device__ __forceinline__ void ffma2(unsigned long long& d,
                                      unsigned long long a, unsigned long long b) {
    asm("fma.rn.f32x2 %0, %1, %2, %0;" : "+l"(d) : "l"(a), "l"(b));
}
__device__ __forceinline__ float2 unpack2(unsigned long long v) {
    float2 f;
    asm("mov.b64 {%0, %1}, %2;" : "=f"(f.x), "=f"(f.y) : "l"(v));
    return f;
}
__device__ __forceinline__ float clampf(float v, float lo, float hi) {
    return fminf(fmaxf(v, lo), hi);
}
__device__ __forceinline__ void stcs4(float* p, float a, float b, float c, float d) {
    asm volatile("st.global.cs.v4.f32 [%0], {%1, %2, %3, %4};"
                 :: "l"(p), "f"(a), "f"(b), "f"(c), "f"(d) : "memory");
}
__device__ __forceinline__ float lerp2(float wx, float wy,
                                       float t00, float t01, float t10, float t11) {
    const float h0 = fmaf(wx, t01 - t00, t00);
    const float h1 = fmaf(wx, t11 - t10, t10);
    return fmaf(wy, h1 - h0, h0);
}

// ---------------------------------------------------------------------------
// Phase 2 worker, GG = g & 1 compile-time (warps uniform in g).
// Window mapping: s=0 positions (A) = {0,2} if GG==0 else {0,1};
//                 s=1 positions (B) = the complement.
// ---------------------------------------------------------------------------
template <int GG>
__device__ __forceinline__ void sample_pair(
    const float* __restrict__ offs,
    const float* __restrict__ x,
    float* __restrict__ out,
    int b, int h, int g, int k)
{
    const int w0 = k << 1;
    const float fh = (float)h;
    const int hm = max(h - 1, 0), hp = min(h + 1, 127);
    const int rm = hm << 7, rc = h << 7, rp = hp << 7;
    const int colL = max(w0 - 2, 0);
    const int colM = w0;
    const int colR = min(w0 + 2, 126);
    const bool k0 = (k == 0), k63 = (k == 63);

    float WX[4][2], WY[4][2];
    int bad = 0;
    #pragma unroll
    for (int pos = 0; pos < 4; pos++) {     // pos = ri*2 + rj
        const int ri = pos >> 1, rj = pos & 1;
        const int s = GG ? ri : rj;          // compile-time
        const int o = (g << 2) + pos;
        const float2 ox2 = *reinterpret_cast<const float2*>(&offs[(o << 7) + w0]);
        const float2 oy2 = *reinterpret_cast<const float2*>(&offs[((o + 16) << 7) + w0]);
        #pragma unroll
        for (int p = 0; p < 2; p++) {
            const int wq = w0 + p;
            const float ix = clampf((float)wq + (p ? ox2.y : ox2.x), 0.0f, 127.0f);
            const float iy = clampf(fh + (p ? oy2.y : oy2.x), 0.0f, 127.0f);
            const float x0f = floorf(ix), y0f = floorf(iy);
            const float wx = ix - x0f, wy = iy - y0f;
            const int x0 = (int)x0f, y0 = (int)y0f;
            const int x1 = min(x0 + 1, 127), y1 = min(y0 + 1, 127);
            const int cx0 = s ? wq : max(wq - 1, 0);
            const int cx1 = s ? min(wq + 1, 127) : wq;
            const int cy0 = s ? h : hm, cy1 = s ? hp : h;
            const bool ok = (x0 == cx0) && (wx == 0.0f || x1 == cx1)
                         && (y0 == cy0) && (wy == 0.0f || y1 == cy1);
            if (!ok) bad |= 1 << (pos * 2 + p);
            WX[pos][p] = wx;
            WY[pos][p] = wy;
        }
    }

    const int cbase = b * 64 + (g << 4);
    const float* pb = x + (cbase << 14);
    float* db = out + (cbase << 16) + (h << 9) + (w0 << 1);   // X = 4k

    // A-positions (s=0) and B-positions (s=1), compile-time per GG.
    const int pA0 = 0;
    const int pA1 = GG ? 1 : 2;
    const int pB0 = GG ? 2 : 1;
    const int pB1 = 3;

    {   // fast path: two shared 2x2 windows per channel (7 LDG.64 total)
        const float* p = pb;
        float* dst = db;
        #pragma unroll 1
        for (int cc = 0; cc < 16; cc++) {
            float vv[4][2];
            // ---- window A: rows rm/rc, cols (w-1, w) per pixel ----
            {
                const float2 L0 = __ldg(reinterpret_cast<const float2*>(p + rm + colL));
                const float2 M0 = __ldg(reinterpret_cast<const float2*>(p + rm + colM));
                const float2 L1 = __ldg(reinterpret_cast<const float2*>(p + rc + colL));
                const float2 M1 = __ldg(reinterpret_cast<const float2*>(p + rc + colM));
                const float a0 = k0 ? L0.x : L0.y;   // (rm, w0-1 clamped)
                const float a1 = k0 ? L1.x : L1.y;   // (rc, w0-1 clamped)
                vv[pA0][0] = lerp2(WX[pA0][0], WY[pA0][0], a0, M0.x, a1, M1.x);
                vv[pA1][0] = lerp2(WX[pA1][0], WY[pA1][0], a0, M0.x, a1, M1.x);
                vv[pA0][1] = lerp2(WX[pA0][1], WY[pA0][1], M0.x, M0.y, M1.x, M1.y);
                vv[pA1][1] = lerp2(WX[pA1][1], WY[pA1][1], M0.x, M0.y, M1.x, M1.y);
                // ---- window B: rows rc/rp, cols (w, w+1) per pixel ----
                const float2 R1 = __ldg(reinterpret_cast<const float2*>(p + rc + colR));
                const float2 M2 = __ldg(reinterpret_cast<const float2*>(p + rp + colM));
                const float2 R2 = __ldg(reinterpret_cast<const float2*>(p + rp + colR));
                const float b1 = k63 ? R1.y : R1.x;  // (rc, w0+2 clamped)
                const float b2 = k63 ? R2.y : R2.x;  // (rp, w0+2 clamped)
                vv[pB0][0] = lerp2(WX[pB0][0], WY[pB0][0], M1.x, M1.y, M2.x, M2.y);
                vv[pB1][0] = lerp2(WX[pB1][0], WY[pB1][0], M1.x, M1.y, M2.x, M2.y);
                vv[pB0][1] = lerp2(WX[pB0][1], WY[pB0][1], M1.y, b1, M2.y, b2);
                vv[pB1][1] = lerp2(WX[pB1][1], WY[pB1][1], M1.y, b1, M2.y, b2);
            }
            // row Y=2h:   X = 4k..4k+3 = [pix0 rj0, pix0 rj1, pix1 rj0, pix1 rj1]
            stcs4(dst,       vv[0][0], vv[1][0], vv[0][1], vv[1][1]);
            stcs4(dst + 256, vv[2][0], vv[3][0], vv[2][1], vv[3][1]);
            p += HW;
            dst += 65536;
        }
    }

    if (bad) {  // cold exact repair (offset escaped predicted window)
        for (int pos = 0; pos < 4; pos++) {
            const int ri = pos >> 1, rj = pos & 1;
            const int o = (g << 2) + pos;
            for (int p_ = 0; p_ < 2; p_++) {
                if (!(bad & (1 << (pos * 2 + p_)))) continue;
                const int wq = w0 + p_;
                const float offx = offs[(o << 7) + wq];
                const float offy = offs[((o + 16) << 7) + wq];
                const float ix = clampf((float)wq + offx, 0.0f, 127.0f);
                const float iy = clampf(fh + offy, 0.0f, 127.0f);
                const float x0f = floorf(ix), y0f = floorf(iy);
                const float wx = ix - x0f, wy = iy - y0f;
                const int x0 = (int)x0f, y0 = (int)y0f;
                const int x1 = min(x0 + 1, 127), y1 = min(y0 + 1, 127);
                const float* p = pb;
                float* dst = db + ri * 256 + (p_ << 1) + rj;
                for (int cc = 0; cc < 16; cc++) {
                    const float u00 = __ldg(p + (y0 << 7) + x0);
                    const float u01 = __ldg(p + (y0 << 7) + x1);
                    const float u10 = __ldg(p + (y1 << 7) + x0);
                    const float u11 = __ldg(p + (y1 << 7) + x1);
                    *dst = (1.0f - wy) * ((1.0f - wx) * u00 + wx * u01)
                         + wy * ((1.0f - wx) * u10 + wx * u11);
                    p += HW;
                    dst += 65536;
                }
            }
        }
    }
}

__global__ __launch_bounds__(256, 5) void dysample_fused(
    const float* __restrict__ x,
    const float* __restrict__ w_off,
    const float* __restrict__ b_off,
    float* __restrict__ out)
{
    __shared__ __align__(16) float ws[64 * 32];     // [c][o]
    __shared__ __align__(16) float offs[32 * 128];  // [o][w]

    const int h   = blockIdx.x;
    const int b   = blockIdx.y;
    const int tid = threadIdx.x;

    for (int i = tid; i < 2048; i += 256) {
        int c = i >> 5, o = i & 31;
        ws[i] = __ldg(&w_off[o * 64 + c]);
    }
    __syncthreads();

    // ---------------- Phase 1: 64->32 matvec for this row (packed f32x2) ----
    {
        const int pg = tid & 63;         // pixel pair: pixels 2pg, 2pg+1
        const int og = tid >> 6;         // och group: 8 och [8og, 8og+8)
        const int p0 = pg << 1;
        const float* xb = x + ((b * 64) << 14) + (h << 7) + p0;

        unsigned long long acc[2][4];    // [pixel][och-pair]
        #pragma unroll
        for (int p = 0; p < 2; p++)
            #pragma unroll
            for (int j = 0; j < 4; j++) acc[p][j] = 0ull;

        #pragma unroll 4
        for (int c = 0; c < 64; c++) {
            const float2 xv = __ldg(reinterpret_cast<const float2*>(xb + (c << 14)));
            const ulonglong2* wq =
                reinterpret_cast<const ulonglong2*>(&ws[c * 32 + (og << 3)]);
            const ulonglong2 wA = wq[0], wB = wq[1];
            const unsigned long long xp0 = pack2(xv.x, xv.x);
            const unsigned long long xp1 = pack2(xv.y, xv.y);
            ffma2(acc[0][0], xp0, wA.x); ffma2(acc[0][1], xp0, wA.y);
            ffma2(acc[0][2], xp0, wB.x); ffma2(acc[0][3], xp0, wB.y);
            ffma2(acc[1][0], xp1, wA.x); ffma2(acc[1][1], xp1, wA.y);
            ffma2(acc[1][2], xp1, wB.x); ffma2(acc[1][3], xp1, wB.y);
        }

        #pragma unroll
        for (int j = 0; j < 4; j++) {
            const float2 f0 = unpack2(acc[0][j]);
            const float2 f1 = unpack2(acc[1][j]);
            #pragma unroll
            for (int e = 0; e < 2; e++) {
                const int o = (og << 3) + (j << 1) + e;
                const float bias = __ldg(&b_off[o]);
                const int dd = (o >> 2) & 1, ii = (o >> 1) & 1, jj = o & 1;
                const float initv = 0.25f * (float)((((dd ? ii : jj) << 1)) - 1);
                float2 v;
                v.x = ((e ? f0.y : f0.x) + bias) * 0.25f + initv;
                v.y = ((e ? f1.y : f1.x) + bias) * 0.25f + initv;
                *reinterpret_cast<float2*>(&offs[(o << 7) + p0]) = v;
            }
        }
    }
    __syncthreads();

    // ---------------- Phase 2: bilinear sampling (pixel pair) --------------
    const int k = tid & 63;
    const int g = tid >> 6;              // warp-uniform
    if ((g & 1) == 0)
        sample_pair<0>(offs, x, out, b, h, g, k);
    else
        sample_pair<1>(offs, x, out, b, h, g, k);
}

extern "C" void kernel_launch(void* const* d_in, const int* in_sizes, int n_in,
                              void* d_out, int out_size)
{
    const float* x     = (const float*)d_in[0];  // [16,64,128,128]
    const float* w_off = (const float*)d_in[1];  // [32,64]
    const float* b_off = (const float*)d_in[2];  // [32]
    float* out = (float*)d_out;                  // [16,64,256,256]

    dysample_fused<<<dim3(128, 16), 256>>>(x, w_off, b_off, out);
    (void)in_sizes; (void)n_in; (void)out_size;
}

// round 15
// speedup vs baseline: 1.0072x; 1.0049x over previous
#include <cuda_runtime.h>

// DySample fused (one kernel): B=16, C=64, H=W=128, scale=2, groups=4
// Phase 1 (block = one (b,h) row): off = (x . w_off^T + b_off)*0.25 + init -> smem
//   (G=4 lane map: thread = 2 consecutive pixels x 8 och; LDG.64 + broadcast LDS)
// Phase 2: thread = (w, z); z selects group-pair, 16 channels per group.
//   init sign s = (g&1)? ri : rj => tap window = s-diagonal 2x2 of the 3x3;
//   7 values serve all 4 positions per channel. Only the ALIGNED column-w taps
//   are loaded from global (3 LDG, 1 wf each); w-1 / w+1 neighbors come from
//   warp shuffles, with single-lane predicated loads patching warp edges.
//   Bilinear as nested lerps; .cs stores. Cold exact-repair for escapes.

#define HW 16384

__device__ __forceinline__ unsigned long long pack2(float a, float b) {
    unsigned long long r;
    asm("mov.b64 %0, {%1, %2};" : "=l"(r) : "f"(a), "f"(b));
    return r;
}
__device__ __forceinline__ void ffma2(unsigned long long& d,
                                      unsigned long long a, unsigned long long b) {
    asm("fma.rn.f32x2 %0, %1, %2, %0;" : "+l"(d) : "l"(a), "l"(b));
}
__device__ __forceinline__ float2 unpack2(unsigned long long v) {
    float2 f;
    asm("mov.b64 {%0, %1}, %2;" : "=f"(f.x), "=f"(f.y) : "l"(v));
    return f;
}
__device__ __forceinline__ float clampf(float v, float lo, float hi) {
    return fminf(fmaxf(v, lo), hi);
}
__device__ __forceinline__ void stcs2(float* p, float a, float b) {
    asm volatile("st.global.cs.v2.f32 [%0], {%1, %2};"
                 :: "l"(p), "f"(a), "f"(b) : "memory");
}
// Predicated pair-load: overwrites a,b from pa,pb iff pred != 0 (no branch).
__device__ __forceinline__ void ldg2_if(float& a, float& b, int pred,
                                        const float* pa, const float* pb) {
    asm volatile("{ .reg .pred p; setp.ne.s32 p, %2, 0;\n\t"
                 "@p ld.global.nc.f32 %0, [%3];\n\t"
                 "@p ld.global.nc.f32 %1, [%4]; }"
                 : "+f"(a), "+f"(b) : "r"(pred), "l"(pa), "l"(pb));
}

__global__ __launch_bounds__(256, 5) void dysample_fused(
    const float* __restrict__ x,
    const float* __restrict__ w_off,
    const float* __restrict__ b_off,
    float* __restrict__ out)
{
    __shared__ __align__(16) float ws[64 * 32];     // [c][o]
    __shared__ __align__(16) float offs[32 * 128];  // [o][w]

    const int h   = blockIdx.x;
    const int b   = blockIdx.y;
    const int tid = threadIdx.x;

    // Stage weights transposed (8 KB, L2-hot after first wave).
    for (int i = tid; i < 2048; i += 256) {
        int c = i >> 5, o = i & 31;
        ws[i] = __ldg(&w_off[o * 64 + c]);
    }
    __syncthreads();

    // ---------------- Phase 1: 64->32 matvec for this row (packed f32x2) ----
    {
        const int pg = tid & 63;         // pixel pair: pixels 2pg, 2pg+1
        const int og = tid >> 6;         // och group: 8 och [8og, 8og+8)
        const int p0 = pg << 1;
        const float* xb = x + ((b * 64) << 14) + (h << 7) + p0;

        unsigned long long acc[2][4];    // [pixel][och-pair]
        #pragma unroll
        for (int p = 0; p < 2; p++)
            #pragma unroll
            for (int j = 0; j < 4; j++) acc[p][j] = 0ull;

        #pragma unroll 4
        for (int c = 0; c < 64; c++) {
            const float2 xv = __ldg(reinterpret_cast<const float2*>(xb + (c << 14)));
            const ulonglong2* wq =
                reinterpret_cast<const ulonglong2*>(&ws[c * 32 + (og << 3)]);
            const ulonglong2 wA = wq[0], wB = wq[1];
            const unsigned long long xp0 = pack2(xv.x, xv.x);
            const unsigned long long xp1 = pack2(xv.y, xv.y);
            ffma2(acc[0][0], xp0, wA.x); ffma2(acc[0][1], xp0, wA.y);
            ffma2(acc[0][2], xp0, wB.x); ffma2(acc[0][3], xp0, wB.y);
            ffma2(acc[1][0], xp1, wA.x); ffma2(acc[1][1], xp1, wA.y);
            ffma2(acc[1][2], xp1, wB.x); ffma2(acc[1][3], xp1, wB.y);
        }

        #pragma unroll
        for (int j = 0; j < 4; j++) {
            const float2 f0 = unpack2(acc[0][j]);
            const float2 f1 = unpack2(acc[1][j]);
            #pragma unroll
            for (int e = 0; e < 2; e++) {
                const int o = (og << 3) + (j << 1) + e;
                const float bias = __ldg(&b_off[o]);
                const int dd = (o >> 2) & 1, ii = (o >> 1) & 1, jj = o & 1;
                const float initv = 0.25f * (float)((((dd ? ii : jj) << 1)) - 1);
                float2 v;
                v.x = ((e ? f0.y : f0.x) + bias) * 0.25f + initv;
                v.y = ((e ? f1.y : f1.x) + bias) * 0.25f + initv;
                *reinterpret_cast<float2*>(&offs[(o << 7) + p0]) = v;
            }
        }
    }
    __syncthreads();

    // ---------------- Phase 2: bilinear sampling --------------------------
    const int w = tid & 127;
    const int z = tid >> 7;              // group-pair selector
    const int lane = tid & 31;
    const float fw = (float)w, fh = (float)h;
    const int wm = max(w - 1, 0), wp = min(w + 1, 127);
    const int hm = max(h - 1, 0), hp = min(h + 1, 127);
    const int rm = hm << 7, rc = h << 7, rp = hp << 7;
    // Warp-edge halo predicates (shfl returns own value at lane edges, which
    // is the correct clamped tap only at w==0 / w==127).
    const int predL = (lane == 0)  && (w != 0);
    const int predR = (lane == 31) && (w != 127);

    #pragma unroll
    for (int gg = 0; gg < 2; gg++) {        // compile-time parity
        const int g = (z << 1) + gg;        // g & 1 == gg

        float WX[4], WY[4];
        int bad = 0;
        #pragma unroll
        for (int pos = 0; pos < 4; pos++) {  // pos = ri*2 + rj
            const int ri = pos >> 1, rj = pos & 1;
            const int s = gg ? ri : rj;      // compile-time
            const int o = (g << 2) + pos;
            const float offx = offs[(o << 7) + w];
            const float offy = offs[((o + 16) << 7) + w];
            const float ix = clampf(fw + offx, 0.0f, 127.0f);
            const float iy = clampf(fh + offy, 0.0f, 127.0f);
            const float x0f = floorf(ix), y0f = floorf(iy);
            const float wx = ix - x0f, wy = iy - y0f;
            const int x0 = (int)x0f, y0 = (int)y0f;
            const int x1 = min(x0 + 1, 127), y1 = min(y0 + 1, 127);
            const int cx0 = s ? w : wm,  cx1 = s ? wp : w;
            const int cy0 = s ? h : hm,  cy1 = s ? hp : h;
            const bool ok = (x0 == cx0) && (wx == 0.0f || x1 == cx1)
                         && (y0 == cy0) && (wy == 0.0f || y1 == cy1);
            if (!ok) bad |= (1 << pos);
            WX[pos] = wx;
            WY[pos] = wy;
        }

        const int cbase = b * 64 + (g << 4);
        const float* pb = x + (cbase << 14);
        float* db = out + (cbase << 16) + (h << 9) + (w << 1);

        {   // fast path: 3 aligned taps + shuffled neighbors per channel
            const float* p = pb;
            float* dst = db;
            #pragma unroll 2
            for (int cc = 0; cc < 16; cc++) {
                const float r01 = __ldg(p + rm + w);
                const float r11 = __ldg(p + rc + w);
                const float r21 = __ldg(p + rp + w);
                float r00 = __shfl_up_sync(0xffffffffu, r01, 1);
                float r10 = __shfl_up_sync(0xffffffffu, r11, 1);
                float r12 = __shfl_down_sync(0xffffffffu, r11, 1);
                float r22 = __shfl_down_sync(0xffffffffu, r21, 1);
                ldg2_if(r00, r10, predL, p + rm + w - 1, p + rc + w - 1);
                ldg2_if(r12, r22, predR, p + rc + w + 1, p + rp + w + 1);

                float v[4];
                #pragma unroll
                for (int pos = 0; pos < 4; pos++) {
                    const int s = gg ? (pos >> 1) : (pos & 1);  // compile-time
                    const float t00 = s ? r11 : r00, t01 = s ? r12 : r01;
                    const float t10 = s ? r21 : r10, t11 = s ? r22 : r11;
                    const float h0 = fmaf(WX[pos], t01 - t00, t00);
                    const float h1 = fmaf(WX[pos], t11 - t10, t10);
                    v[pos] = fmaf(WY[pos], h1 - h0, h0);
                }
                stcs2(dst,       v[0], v[1]);   // row Y=2h
                stcs2(dst + 256, v[2], v[3]);   // row Y=2h+1
                p += HW;
                dst += 65536;
            }
        }

        if (bad) {  // cold exact repair (offset escaped predicted window)
            for (int pos = 0; pos < 4; pos++) {
                if (!(bad & (1 << pos))) continue;
                const int o = (g << 2) + pos;
                const float offx = offs[(o << 7) + w];
                const float offy = offs[((o + 16) << 7) + w];
                const float ix = clampf(fw + offx, 0.0f, 127.0f);
                const float iy = clampf(fh + offy, 0.0f, 127.0f);
                const float x0f = floorf(ix), y0f = floorf(iy);
                const float wx = ix - x0f, wy = iy - y0f;
                const int x0 = (int)x0f, y0 = (int)y0f;
                const int x1 = min(x0 + 1, 127), y1 = min(y0 + 1, 127);
                const float* p = pb;
                float* dst = db + (pos >> 1) * 256 + (pos & 1);
                for (int cc = 0; cc < 16; cc++) {
                    const float u00 = __ldg(p + (y0 << 7) + x0);
                    const float u01 = __ldg(p + (y0 << 7) + x1);
                    const float u10 = __ldg(p + (y1 << 7) + x0);
                    const float u11 = __ldg(p + (y1 << 7) + x1);
                    *dst = (1.0f - wy) * ((1.0f - wx) * u00 + wx * u01)
                         + wy * ((1.0f - wx) * u10 + wx * u11);
                    p += HW;
                    dst += 65536;
                }
            }
        }
    }
}

extern "C" void kernel_launch(void* const* d_in, const int* in_sizes, int n_in,
                              void* d_out, int out_size)
{
    const float* x     = (const float*)d_in[0];  // [16,64,128,128]
    const float* w_off = (const float*)d_in[1];  // [32,64]
    const float* b_off = (const float*)d_in[2];  // [32]
    float* out = (float*)d_out;                  // [16,64,256,256]

    dysample_fused<<<dim3(128, 16), 256>>>(x, w_off, b_off, out);
    (void)in_sizes; (void)n_in; (void)out_size;
}